// round 13
// baseline (speedup 1.0000x reference)
#include <cuda_runtime.h>
#include <cuda_fp16.h>
#include <cstdint>

#define BBATCH 16384

__device__ float g_center[BBATCH * 256];
__device__ float g_cd[BBATCH * 128];
__device__ float g_gate[BBATCH * 256];
__device__ __align__(16) __half g_comb_h[BBATCH * 256];
// fp16 weight images, chunk-major [chunk][n(128)][64]:
//   [0,32768): W1 neighbor | [32768,65536): W1 center | [65536,98304): gate_W h0,h1
__device__ __align__(16) __half g_Bh[98304];
// out_W image: [nhalf][chunk][n(128)][64]
__device__ __align__(16) __half g_oWh[65536];

// ---- smem layout for k0/k3 (double-buffered chunked gemm; 2 CTA/SM) ----
#define SA    0          // 67584: A fp16 [128 rows][264] (stride 528B)
#define SBUF  67584      // 36864: 2 x B chunk [128 n][72 k fp16] (stride 144B)
#define SIDX  111104     // 512
#define SM_BYTES 112640

// ---- smem layout for k1 (18 warps) ----
#define K1_B    0          // 65536: full W1nb image, 4 chunks, XOR-swizzled
#define K1_A    65536      // 147456: 18 warps x 8KB A region (16 rows x 512B, XOR)
#define K1_W2   212992     // 512
#define K1_B2   213504     // 16
#define K1_LG   213520     // 2304: per-warp 32-float scratch
#define K1_BYTES 216064

__device__ __forceinline__ uint32_t smem_u32(const void* p) {
    uint32_t a;
    asm("{ .reg .u64 t; cvta.to.shared.u64 t, %1; cvt.u32.u64 %0, t; }" : "=r"(a) : "l"(p));
    return a;
}
__device__ __forceinline__ void ldsm_x4(uint32_t& r0, uint32_t& r1, uint32_t& r2, uint32_t& r3, uint32_t addr) {
    asm volatile("ldmatrix.sync.aligned.m8n8.x4.shared.b16 {%0,%1,%2,%3}, [%4];"
                 : "=r"(r0), "=r"(r1), "=r"(r2), "=r"(r3) : "r"(addr));
}
__device__ __forceinline__ void mma16816(float* d, uint32_t a0, uint32_t a1, uint32_t a2, uint32_t a3,
                                         uint32_t b0, uint32_t b1) {
    asm volatile(
        "mma.sync.aligned.m16n8k16.row.col.f32.f16.f16.f32 "
        "{%0,%1,%2,%3}, {%4,%5,%6,%7}, {%8,%9}, {%0,%1,%2,%3};"
        : "+f"(d[0]), "+f"(d[1]), "+f"(d[2]), "+f"(d[3])
        : "r"(a0), "r"(a1), "r"(a2), "r"(a3), "r"(b0), "r"(b1));
}
__device__ __forceinline__ void cp16(uint32_t saddr, const void* g) {
    asm volatile("cp.async.ca.shared.global [%0], [%1], 16;" :: "r"(saddr), "l"(g));
}
__device__ __forceinline__ void cp_commit() { asm volatile("cp.async.commit_group;"); }
__device__ __forceinline__ void cp_wait0()  { asm volatile("cp.async.wait_group 0;" ::: "memory"); }
// exact GELU via erff polynomial (pure FFMA pipe -- faster here than MUFU paths)
__device__ __forceinline__ float gelu_exact(float x) {
    return 0.5f * x * (1.0f + erff(x * 0.70710678118654752440f));
}

// ---------------------------------------------------------------------------
__global__ __launch_bounds__(256) void prep_pack(const float* __restrict__ W1,
                                                 const float* __restrict__ gW,
                                                 const float* __restrict__ oW) {
    int i = blockIdx.x * 256 + threadIdx.x;
    if (i < 65536) {
        int img = i >> 15;
        int r = i & 32767;
        int chunk = r >> 13;
        int rr = r & 8191;
        int n = rr >> 6, kl = rr & 63;
        int k = chunk * 64 + kl;
        int h = n >> 6, a = n & 63;
        int es = img ? k : (256 + k);
        g_Bh[i] = __float2half_rn(W1[(size_t)h * 32768 + (size_t)es * 64 + a]);
    } else if (i < 98304) {
        int j = i - 65536;
        int h = j >> 14;
        int rr = j & 16383;
        int chunk = rr >> 13;
        int r2 = rr & 8191;
        int d = r2 >> 6, el = r2 & 63;
        int e = chunk * 64 + el;
        g_Bh[i] = __float2half_rn(gW[(size_t)h * 16384 + (size_t)d * 128 + e]);
    } else {
        int j = i - 98304;
        int nh = j >> 15;
        int r = j & 32767;
        int chunk = r >> 13;
        int rr = r & 8191;
        int n = rr >> 6, kl = rr & 63;
        int k = chunk * 64 + kl;
        int N = nh * 128 + n;
        g_oWh[j] = __float2half_rn(oW[(size_t)N * 256 + k]);
    }
}

// ---- chunked gemm machinery (k0/k3), double-buffered ----
__device__ __forceinline__ void load_chunk(uint32_t sdst, const __half* src, int tid) {
    #pragma unroll
    for (int t = 0; t < 4; t++) {
        const int i = tid + t * 256;
        const int row = i >> 3, seg = i & 7;
        cp16(sdst + row * 144 + seg * 16, src + row * 64 + seg * 8);
    }
}
__device__ __forceinline__ void gemm_chunks(float acc[16][4], uint32_t smb,
                                            const __half* gB, int nchunks,
                                            int a_k_byte, int tid) {
    const int warp = tid >> 5, lane = tid & 31;
    const uint32_t aBase = smb + SA + (uint32_t)(warp * 16 + (lane & 15)) * 528
                         + (uint32_t)((lane >> 4) * 16) + (uint32_t)a_k_byte;
    const int bg = lane >> 3, br = lane & 7;
    const uint32_t bOff = (uint32_t)(br + ((bg >> 1) * 8)) * 144 + (uint32_t)((bg & 1) * 16);

    load_chunk(smb + SBUF, gB, tid);
    cp_commit();
    for (int c = 0; c < nchunks; c++) {
        cp_wait0();
        __syncthreads();
        if (c + 1 < nchunks) {
            load_chunk(smb + SBUF + ((c + 1) & 1) * 18432, gB + (c + 1) * 8192, tid);
            cp_commit();
        }
        const uint32_t bBase = smb + SBUF + (c & 1) * 18432 + bOff;
        const uint32_t aC = aBase + c * 128;
        #pragma unroll
        for (int kt = 0; kt < 4; kt++) {
            uint32_t a0, a1, a2, a3;
            ldsm_x4(a0, a1, a2, a3, aC + kt * 32);
            #pragma unroll
            for (int np = 0; np < 8; np++) {
                uint32_t b0, b1, b2, b3;
                ldsm_x4(b0, b1, b2, b3, bBase + (uint32_t)(np * 2304) + kt * 32);
                mma16816(acc[2 * np],     a0, a1, a2, a3, b0, b1);
                mma16816(acc[2 * np + 1], a0, a1, a2, a3, b2, b3);
            }
        }
        __syncthreads();
    }
}

// ---------------------------------------------------------------------------
// k0: centers -> g_center, g_cd, g_gate. grid.y: y0 = cd (+store center),
// y1 = both gate gemms.
__global__ __launch_bounds__(256) void k0_center(
    const int* __restrict__ cidx, const float* __restrict__ emb,
    const float* __restrict__ b1, const float* __restrict__ gb)
{
    extern __shared__ __align__(16) char smp[];
    const uint32_t smb = smem_u32(smp);
    const int tid = threadIdx.x, warp = tid >> 5, lane = tid & 31;
    const int b0 = blockIdx.x * 128;
    const int job = blockIdx.y;

    int* sIdx = (int*)(smp + SIDX);
    if (tid < 128) sIdx[tid] = cidx[b0 + tid];
    __syncthreads();

    for (int i = tid; i < 8192; i += 256) {
        const int row = i >> 6;
        const int e0 = (i & 63) * 4;
        const int ci = sIdx[row];
        float4 v = make_float4(0.f, 0.f, 0.f, 0.f);
        if (ci >= 0) v = *(const float4*)(emb + (size_t)ci * 256 + e0);
        if (job == 0) *(float4*)(g_center + (size_t)(b0 + row) * 256 + e0) = v;
        __half2 h0 = __floats2half2_rn(v.x, v.y);
        __half2 h1 = __floats2half2_rn(v.z, v.w);
        *(uint2*)(smp + SA + row * 528 + e0 * 2) = make_uint2(*(uint32_t*)&h0, *(uint32_t*)&h1);
    }
    __syncthreads();

    const int r0l = warp * 16 + (lane >> 2);
    float acc[16][4];

    if (job == 0) {
        #pragma unroll
        for (int i = 0; i < 16; i++)
            acc[i][0] = acc[i][1] = acc[i][2] = acc[i][3] = 0.f;
        gemm_chunks(acc, smb, g_Bh + 32768, 4, 0, tid);
        #pragma unroll
        for (int nt = 0; nt < 16; nt++) {
            const int n0 = nt * 8 + (lane & 3) * 2;
            g_cd[(size_t)(b0 + r0l) * 128 + n0]           = acc[nt][0] + b1[n0];
            g_cd[(size_t)(b0 + r0l) * 128 + n0 + 1]       = acc[nt][1] + b1[n0 + 1];
            g_cd[(size_t)(b0 + r0l + 8) * 128 + n0]       = acc[nt][2] + b1[n0];
            g_cd[(size_t)(b0 + r0l + 8) * 128 + n0 + 1]   = acc[nt][3] + b1[n0 + 1];
        }
    } else {
        #pragma unroll
        for (int h = 0; h < 2; h++) {
            #pragma unroll
            for (int i = 0; i < 16; i++)
                acc[i][0] = acc[i][1] = acc[i][2] = acc[i][3] = 0.f;
            __syncthreads();
            gemm_chunks(acc, smb, g_Bh + 65536 + h * 16384, 2, h * 256, tid);
            #pragma unroll
            for (int nt = 0; nt < 16; nt++) {
                const int d0 = nt * 8 + (lane & 3) * 2;
                const float g0 = gb[h * 128 + d0], g1 = gb[h * 128 + d0 + 1];
                float* outA = g_gate + (size_t)(b0 + r0l) * 256 + h * 128;
                float* outB = g_gate + (size_t)(b0 + r0l + 8) * 256 + h * 128;
                outA[d0]     = 1.0f / (1.0f + __expf(-(acc[nt][0] + g0)));
                outA[d0 + 1] = 1.0f / (1.0f + __expf(-(acc[nt][1] + g1)));
                outB[d0]     = 1.0f / (1.0f + __expf(-(acc[nt][2] + g0)));
                outB[d0 + 1] = 1.0f / (1.0f + __expf(-(acc[nt][3] + g1)));
            }
        }
    }
}

// ---------------------------------------------------------------------------
// k1: warp-autonomous persistent. 148 blocks x 576 thr (18 warps). B resident.
__global__ __launch_bounds__(576, 1) void k1_main(
    const int*   __restrict__ cidx,
    const float* __restrict__ emb,
    const int*   __restrict__ nbidx,
    const float* __restrict__ nbwt,
    const float* __restrict__ W2,
    const float* __restrict__ b2,
    int B)
{
    extern __shared__ __align__(16) char smp[];
    const uint32_t smb = smem_u32(smp);
    const int tid = threadIdx.x, warp = tid >> 5, lane = tid & 31;

    // stage full W1nb image (XOR-swizzled) + W2/b2; one block sync
    for (int i = tid; i < 4096; i += 576) {
        const int chunk = i >> 10;
        const int rem = i & 1023;
        const int n = rem >> 3, s = rem & 7;
        cp16(smb + K1_B + chunk * 16384 + n * 128 + ((s * 16) ^ ((n & 7) << 4)),
             g_Bh + chunk * 8192 + n * 64 + s * 8);
    }
    cp_commit();
    if (tid < 128) ((float*)(smp + K1_W2))[tid] = W2[tid];
    if (tid < 2)   ((float*)(smp + K1_B2))[tid] = b2[tid];
    cp_wait0();
    __syncthreads();

    const float* sW2 = (const float*)(smp + K1_W2);
    const float* sB2 = (const float*)(smp + K1_B2);
    float* sLg = (float*)(smp + K1_LG) + warp * 32;
    const uint32_t AwOff = (uint32_t)K1_A + (uint32_t)warp * 8192;

    const uint32_t aLdsm = smb + AwOff + (uint32_t)(lane & 15) * 512;
    const uint32_t aXor  = (uint32_t)((lane & 7) << 4);
    const int bg = lane >> 3, br = lane & 7;
    const int bRowL = br + ((bg >> 1) << 3);
    const uint32_t bColB = (uint32_t)((bg & 1) << 4);
    const uint32_t bXor  = (uint32_t)((bRowL & 7) << 4);

    const int wg = blockIdx.x * 18 + warp;
    const int NW = gridDim.x * 18;

    int gidx = 0, msk = 0; float wt = 0.f;
    {
        const int b = wg;
        if (b < B) {
            int ci = 0;
            if (lane == 0) ci = cidx[b];
            ci = __shfl_sync(0xffffffffu, ci, 0);
            const int safe = ci >= 0 ? ci : 0;
            if (lane < 16) {
                const int ni = nbidx[(size_t)safe * 16 + lane];
                msk = ni >= 0;
                gidx = ni >= 0 ? ni : 0;
                wt = nbwt[(size_t)safe * 16 + lane];
            }
        }
    }

    for (int b = wg; b < B; b += NW) {
        const size_t bofs = (size_t)b * 256;

        #pragma unroll
        for (int r = 0; r < 16; r++) {
            const int src = __shfl_sync(0xffffffffu, gidx, r);
            const float4 v0 = *(const float4*)(emb + (size_t)src * 256 + lane * 8);
            const float4 v1 = *(const float4*)(emb + (size_t)src * 256 + lane * 8 + 4);
            __half2 h0 = __floats2half2_rn(v0.x, v0.y);
            __half2 h1 = __floats2half2_rn(v0.z, v0.w);
            __half2 h2 = __floats2half2_rn(v1.x, v1.y);
            __half2 h3 = __floats2half2_rn(v1.z, v1.w);
            uint4 pk = make_uint4(*(uint32_t*)&h0, *(uint32_t*)&h1, *(uint32_t*)&h2, *(uint32_t*)&h3);
            *(uint4*)(smp + AwOff + r * 512 + (((uint32_t)(lane * 16)) ^ ((r & 7) << 4))) = pk;
        }
        const int mskC = msk; const float wtC = wt;

        // L2 prefetch of gate/center lines consumed in the combine phase
        if (lane < 16) {
            const char* base = (lane < 8) ? (const char*)(g_gate + bofs)
                                          : (const char*)(g_center + bofs);
            asm volatile("prefetch.global.L2 [%0];" :: "l"(base + (size_t)(lane & 7) * 128));
        }

        // prefetch next-b metadata
        {
            const int bn = b + NW;
            if (bn < B) {
                int ci = 0;
                if (lane == 0) ci = cidx[bn];
                ci = __shfl_sync(0xffffffffu, ci, 0);
                const int safe = ci >= 0 ? ci : 0;
                if (lane < 16) {
                    const int ni = nbidx[(size_t)safe * 16 + lane];
                    msk = ni >= 0;
                    gidx = ni >= 0 ? ni : 0;
                    wt = nbwt[(size_t)safe * 16 + lane];
                }
            }
        }

        // preload cd halves (hides under MMA)
        float2 cdr[8];
        {
            const float* cdb = g_cd + (size_t)b * 128;
            #pragma unroll
            for (int nt = 0; nt < 8; nt++)
                cdr[nt] = *(const float2*)(cdb + nt * 16 + (lane & 3) * 2);
        }
        __syncwarp();

        float acc[16][4];
        #pragma unroll
        for (int i = 0; i < 16; i++)
            acc[i][0] = acc[i][1] = acc[i][2] = acc[i][3] = 0.f;
        #pragma unroll
        for (int c = 0; c < 4; c++) {
            const uint32_t Bc = smb + K1_B + c * 16384;
            #pragma unroll
            for (int kt = 0; kt < 4; kt++) {
                const uint32_t aCol = (uint32_t)(c * 128 + kt * 32) + ((uint32_t)(lane >> 4) << 4);
                uint32_t a0, a1, a2, a3;
                ldsm_x4(a0, a1, a2, a3, aLdsm + (aCol ^ aXor));
                const uint32_t bCol = ((uint32_t)(kt * 32) + bColB) ^ bXor;
                #pragma unroll
                for (int np = 0; np < 8; np++) {
                    uint32_t b0, b1, b2r, b3;
                    ldsm_x4(b0, b1, b2r, b3, Bc + (uint32_t)((np * 16 + bRowL) * 128) + bCol);
                    mma16816(acc[2 * np],     a0, a1, a2, a3, b0, b1);
                    mma16816(acc[2 * np + 1], a0, a1, a2, a3, b2r, b3);
                }
            }
        }

        float lgA[2] = {0.f, 0.f};
        float lgB[2] = {0.f, 0.f};
        const float* cdb = g_cd + (size_t)b * 128;
        #pragma unroll
        for (int nt = 0; nt < 16; nt++) {
            const int h = nt >> 3;
            const int n0 = nt * 8 + (lane & 3) * 2;
            float2 cd2;
            if ((nt & 1) == 0) cd2 = cdr[nt >> 1];
            else               cd2 = *(const float2*)(cdb + n0);
            const float w20 = sW2[n0], w21 = sW2[n0 + 1];
            lgA[h] += gelu_exact(acc[nt][0] + cd2.x) * w20 + gelu_exact(acc[nt][1] + cd2.y) * w21;
            lgB[h] += gelu_exact(acc[nt][2] + cd2.x) * w20 + gelu_exact(acc[nt][3] + cd2.y) * w21;
        }
        #pragma unroll
        for (int s = 1; s < 4; s <<= 1) {
            lgA[0] += __shfl_xor_sync(0xffffffffu, lgA[0], s);
            lgA[1] += __shfl_xor_sync(0xffffffffu, lgA[1], s);
            lgB[0] += __shfl_xor_sync(0xffffffffu, lgB[0], s);
            lgB[1] += __shfl_xor_sync(0xffffffffu, lgB[1], s);
        }
        if ((lane & 3) == 0) {
            const int k = lane >> 2;
            sLg[k]          = lgA[0];
            sLg[16 + k]     = lgA[1];
            sLg[k + 8]      = lgB[0];
            sLg[16 + k + 8] = lgB[1];
        }
        __syncwarp();

        {
            const int hh = lane >> 4;
            const int k = lane & 15;
            const int mk = __shfl_sync(0xffffffffu, mskC, k);
            const float wk = __shfl_sync(0xffffffffu, wtC, k);
            const float NEG_INF = __int_as_float(0xff800000);
            float lv = sLg[hh * 16 + k] + sB2[hh] + __logf(wk + 1e-8f);
            if (!mk) lv = NEG_INF;
            float mx = lv;
            #pragma unroll
            for (int s = 1; s < 16; s <<= 1)
                mx = fmaxf(mx, __shfl_xor_sync(0xffffffffu, mx, s));
            const bool none = (mx == NEG_INF);
            float ex = mk ? __expf(lv - (none ? 0.f : mx)) : 0.f;
            float sm = ex;
            #pragma unroll
            for (int s = 1; s < 16; s <<= 1)
                sm += __shfl_xor_sync(0xffffffffu, sm, s);
            __syncwarp();
            sLg[hh * 16 + k] = none ? (1.0f / 16.0f) : (ex / sm);
        }
        __syncwarp();

        #pragma unroll
        for (int j = 0; j < 4; j++) {
            const int e = j * 64 + lane * 2;
            const float* wgt = sLg + ((j >> 1) << 4);
            float ax = 0.f, ay = 0.f;
            #pragma unroll
            for (int k = 0; k < 16; k++) {
                const uint32_t ad = AwOff + k * 512 + (((uint32_t)(e * 2)) ^ ((uint32_t)(k & 7) << 4));
                const __half2 hv = *(const __half2*)(smp + ad);
                const float2 f = __half22float2(hv);
                ax = fmaf(wgt[k], f.x, ax);
                ay = fmaf(wgt[k], f.y, ay);
            }
            const float2 gt = *(const float2*)(g_gate + bofs + e);
            const float2 cn = *(const float2*)(g_center + bofs + e);
            *(__half2*)(g_comb_h + bofs + e) =
                __floats2half2_rn(fmaf(gt.x, ax, cn.x), fmaf(gt.y, ay, cn.y));
        }
        __syncwarp();
    }
}

// ---------------------------------------------------------------------------
// k3: out = comb_h @ oW^T + ob (HMMA). grid.y = n-half.
__global__ __launch_bounds__(256) void k3_out_h(
    const float* __restrict__ ob,
    const int*   __restrict__ cidx,
    float*       __restrict__ out)
{
    extern __shared__ __align__(16) char smp[];
    const uint32_t smb = smem_u32(smp);
    const int tid = threadIdx.x, warp = tid >> 5, lane = tid & 31;
    const int b0 = blockIdx.x * 128;
    const int nh = blockIdx.y;

    for (int i = tid; i < 4096; i += 256) {
        const int row = i >> 5, seg = i & 31;
        *(uint4*)(smp + SA + row * 528 + seg * 16) =
            *(const uint4*)(g_comb_h + (size_t)(b0 + row) * 256 + seg * 8);
    }
    __syncthreads();

    const int r0 = b0 + warp * 16 + (lane >> 2);
    const int ci0 = cidx[r0], ci1 = cidx[r0 + 8];

    float acc[16][4];
    #pragma unroll
    for (int i = 0; i < 16; i++)
        acc[i][0] = acc[i][1] = acc[i][2] = acc[i][3] = 0.f;
    gemm_chunks(acc, smb, g_oWh + nh * 32768, 4, 0, tid);
    #pragma unroll
    for (int nt = 0; nt < 16; nt++) {
        const int n0 = nh * 128 + nt * 8 + (lane & 3) * 2;
        float yA0 = acc[nt][0] + ob[n0];
        float yA1 = acc[nt][1] + ob[n0 + 1];
        float yB0 = acc[nt][2] + ob[n0];
        float yB1 = acc[nt][3] + ob[n0 + 1];
        if (ci0 < 0) {
            yA0 = g_center[(size_t)r0 * 256 + n0];
            yA1 = g_center[(size_t)r0 * 256 + n0 + 1];
        }
        if (ci1 < 0) {
            yB0 = g_center[(size_t)(r0 + 8) * 256 + n0];
            yB1 = g_center[(size_t)(r0 + 8) * 256 + n0 + 1];
        }
        out[(size_t)r0 * 256 + n0]           = yA0;
        out[(size_t)r0 * 256 + n0 + 1]       = yA1;
        out[(size_t)(r0 + 8) * 256 + n0]     = yB0;
        out[(size_t)(r0 + 8) * 256 + n0 + 1] = yB1;
    }
}

// ---------------------------------------------------------------------------
extern "C" void kernel_launch(void* const* d_in, const int* in_sizes, int n_in,
                              void* d_out, int out_size)
{
    const int*   center_idx = (const int*)  d_in[0];
    const float* emb        = (const float*)d_in[1];
    const int*   nbidx      = (const int*)  d_in[2];
    const float* nbwt       = (const float*)d_in[3];
    const float* W1         = (const float*)d_in[4];
    const float* b1         = (const float*)d_in[5];
    const float* W2         = (const float*)d_in[6];
    const float* b2         = (const float*)d_in[7];
    const float* gW         = (const float*)d_in[8];
    const float* gb         = (const float*)d_in[9];
    const float* oW         = (const float*)d_in[10];
    const float* ob         = (const float*)d_in[11];
    float* out = (float*)d_out;
    const int B = in_sizes[0];

    cudaFuncSetAttribute(k0_center, cudaFuncAttributeMaxDynamicSharedMemorySize, SM_BYTES);
    cudaFuncSetAttribute(k1_main,   cudaFuncAttributeMaxDynamicSharedMemorySize, K1_BYTES);
    cudaFuncSetAttribute(k3_out_h,  cudaFuncAttributeMaxDynamicSharedMemorySize, SM_BYTES);

    prep_pack<<<640, 256>>>(W1, gW, oW);
    k0_center<<<dim3(B / 128, 2), 256, SM_BYTES>>>(center_idx, emb, b1, gb);
    k1_main<<<148, 576, K1_BYTES>>>(center_idx, emb, nbidx, nbwt, W2, b2, B);
    k3_out_h<<<dim3(B / 128, 2), 256, SM_BYTES>>>(ob, center_idx, out);
}

// round 14
// speedup vs baseline: 1.1932x; 1.1932x over previous
#include <cuda_runtime.h>
#include <cuda_fp16.h>
#include <cstdint>

#define BBATCH 16384

__device__ float g_center[BBATCH * 256];
__device__ float g_cd[BBATCH * 128];
__device__ float g_gate[BBATCH * 256];
__device__ __align__(16) __half g_comb_h[BBATCH * 256];
// fp16 weight images, chunk-major [chunk][n(128)][64]:
//   [0,32768): W1 neighbor | [32768,65536): W1 center | [65536,98304): gate_W h0,h1
__device__ __align__(16) __half g_Bh[98304];
// out_W image: [nhalf][chunk][n(128)][64]
__device__ __align__(16) __half g_oWh[65536];

// ---- smem layout for k0/k3 (double-buffered chunked gemm; 2 CTA/SM) ----
#define SA    0          // 67584: A fp16 [128 rows][264] (stride 528B)
#define SBUF  67584      // 36864: 2 x B chunk [128 n][72 k fp16] (stride 144B)
#define SIDX  111104     // 512
#define SM_BYTES 112640

// ---- smem layout for k1 (16 warps, 512 threads) ----
#define K1_B    0          // 65536: full W1nb image, 4 chunks, XOR-swizzled
#define K1_A    65536      // 131072: 16 warps x 8KB A region (16 rows x 512B, XOR)
#define K1_W2   196608     // 512
#define K1_B2   197120     // 8
#define K1_LG   197632     // 2048
#define K1_BYTES 199680

__device__ __forceinline__ uint32_t smem_u32(const void* p) {
    uint32_t a;
    asm("{ .reg .u64 t; cvta.to.shared.u64 t, %1; cvt.u32.u64 %0, t; }" : "=r"(a) : "l"(p));
    return a;
}
__device__ __forceinline__ void ldsm_x4(uint32_t& r0, uint32_t& r1, uint32_t& r2, uint32_t& r3, uint32_t addr) {
    asm volatile("ldmatrix.sync.aligned.m8n8.x4.shared.b16 {%0,%1,%2,%3}, [%4];"
                 : "=r"(r0), "=r"(r1), "=r"(r2), "=r"(r3) : "r"(addr));
}
__device__ __forceinline__ void mma16816(float* d, uint32_t a0, uint32_t a1, uint32_t a2, uint32_t a3,
                                         uint32_t b0, uint32_t b1) {
    asm volatile(
        "mma.sync.aligned.m16n8k16.row.col.f32.f16.f16.f32 "
        "{%0,%1,%2,%3}, {%4,%5,%6,%7}, {%8,%9}, {%0,%1,%2,%3};"
        : "+f"(d[0]), "+f"(d[1]), "+f"(d[2]), "+f"(d[3])
        : "r"(a0), "r"(a1), "r"(a2), "r"(a3), "r"(b0), "r"(b1));
}
__device__ __forceinline__ void cp16(uint32_t saddr, const void* g) {
    asm volatile("cp.async.ca.shared.global [%0], [%1], 16;" :: "r"(saddr), "l"(g));
}
__device__ __forceinline__ void cp_commit() { asm volatile("cp.async.commit_group;"); }
__device__ __forceinline__ void cp_wait0()  { asm volatile("cp.async.wait_group 0;" ::: "memory"); }
// exact GELU via erff polynomial (pure FFMA pipe)
__device__ __forceinline__ float gelu_exact(float x) {
    return 0.5f * x * (1.0f + erff(x * 0.70710678118654752440f));
}

// ---------------------------------------------------------------------------
__global__ __launch_bounds__(256) void prep_pack(const float* __restrict__ W1,
                                                 const float* __restrict__ gW,
                                                 const float* __restrict__ oW) {
    int i = blockIdx.x * 256 + threadIdx.x;
    if (i < 65536) {
        int img = i >> 15;
        int r = i & 32767;
        int chunk = r >> 13;
        int rr = r & 8191;
        int n = rr >> 6, kl = rr & 63;
        int k = chunk * 64 + kl;
        int h = n >> 6, a = n & 63;
        int es = img ? k : (256 + k);
        g_Bh[i] = __float2half_rn(W1[(size_t)h * 32768 + (size_t)es * 64 + a]);
    } else if (i < 98304) {
        int j = i - 65536;
        int h = j >> 14;
        int rr = j & 16383;
        int chunk = rr >> 13;
        int r2 = rr & 8191;
        int d = r2 >> 6, el = r2 & 63;
        int e = chunk * 64 + el;
        g_Bh[i] = __float2half_rn(gW[(size_t)h * 16384 + (size_t)d * 128 + e]);
    } else {
        int j = i - 98304;
        int nh = j >> 15;
        int r = j & 32767;
        int chunk = r >> 13;
        int rr = r & 8191;
        int n = rr >> 6, kl = rr & 63;
        int k = chunk * 64 + kl;
        int N = nh * 128 + n;
        g_oWh[j] = __float2half_rn(oW[(size_t)N * 256 + k]);
    }
}

// ---- chunked gemm machinery (k0/k3), double-buffered ----
__device__ __forceinline__ void load_chunk(uint32_t sdst, const __half* src, int tid) {
    #pragma unroll
    for (int t = 0; t < 4; t++) {
        const int i = tid + t * 256;
        const int row = i >> 3, seg = i & 7;
        cp16(sdst + row * 144 + seg * 16, src + row * 64 + seg * 8);
    }
}
__device__ __forceinline__ void gemm_chunks(float acc[16][4], uint32_t smb,
                                            const __half* gB, int nchunks,
                                            int a_k_byte, int tid) {
    const int warp = tid >> 5, lane = tid & 31;
    const uint32_t aBase = smb + SA + (uint32_t)(warp * 16 + (lane & 15)) * 528
                         + (uint32_t)((lane >> 4) * 16) + (uint32_t)a_k_byte;
    const int bg = lane >> 3, br = lane & 7;
    const uint32_t bOff = (uint32_t)(br + ((bg >> 1) * 8)) * 144 + (uint32_t)((bg & 1) * 16);

    load_chunk(smb + SBUF, gB, tid);
    cp_commit();
    for (int c = 0; c < nchunks; c++) {
        cp_wait0();
        __syncthreads();
        if (c + 1 < nchunks) {
            load_chunk(smb + SBUF + ((c + 1) & 1) * 18432, gB + (c + 1) * 8192, tid);
            cp_commit();
        }
        const uint32_t bBase = smb + SBUF + (c & 1) * 18432 + bOff;
        const uint32_t aC = aBase + c * 128;
        #pragma unroll
        for (int kt = 0; kt < 4; kt++) {
            uint32_t a0, a1, a2, a3;
            ldsm_x4(a0, a1, a2, a3, aC + kt * 32);
            #pragma unroll
            for (int np = 0; np < 8; np++) {
                uint32_t b0, b1, b2, b3;
                ldsm_x4(b0, b1, b2, b3, bBase + (uint32_t)(np * 2304) + kt * 32);
                mma16816(acc[2 * np],     a0, a1, a2, a3, b0, b1);
                mma16816(acc[2 * np + 1], a0, a1, a2, a3, b2, b3);
            }
        }
        __syncthreads();
    }
}

// ---------------------------------------------------------------------------
// k0: centers -> g_center, g_cd, g_gate. grid.y: y0 = cd (+store center),
// y1 = both gate gemms.
__global__ __launch_bounds__(256) void k0_center(
    const int* __restrict__ cidx, const float* __restrict__ emb,
    const float* __restrict__ b1, const float* __restrict__ gb)
{
    extern __shared__ __align__(16) char smp[];
    const uint32_t smb = smem_u32(smp);
    const int tid = threadIdx.x, warp = tid >> 5, lane = tid & 31;
    const int b0 = blockIdx.x * 128;
    const int job = blockIdx.y;

    int* sIdx = (int*)(smp + SIDX);
    if (tid < 128) sIdx[tid] = cidx[b0 + tid];
    __syncthreads();

    for (int i = tid; i < 8192; i += 256) {
        const int row = i >> 6;
        const int e0 = (i & 63) * 4;
        const int ci = sIdx[row];
        float4 v = make_float4(0.f, 0.f, 0.f, 0.f);
        if (ci >= 0) v = *(const float4*)(emb + (size_t)ci * 256 + e0);
        if (job == 0) *(float4*)(g_center + (size_t)(b0 + row) * 256 + e0) = v;
        __half2 h0 = __floats2half2_rn(v.x, v.y);
        __half2 h1 = __floats2half2_rn(v.z, v.w);
        *(uint2*)(smp + SA + row * 528 + e0 * 2) = make_uint2(*(uint32_t*)&h0, *(uint32_t*)&h1);
    }
    __syncthreads();

    const int r0l = warp * 16 + (lane >> 2);
    float acc[16][4];

    if (job == 0) {
        #pragma unroll
        for (int i = 0; i < 16; i++)
            acc[i][0] = acc[i][1] = acc[i][2] = acc[i][3] = 0.f;
        gemm_chunks(acc, smb, g_Bh + 32768, 4, 0, tid);
        #pragma unroll
        for (int nt = 0; nt < 16; nt++) {
            const int n0 = nt * 8 + (lane & 3) * 2;
            g_cd[(size_t)(b0 + r0l) * 128 + n0]           = acc[nt][0] + b1[n0];
            g_cd[(size_t)(b0 + r0l) * 128 + n0 + 1]       = acc[nt][1] + b1[n0 + 1];
            g_cd[(size_t)(b0 + r0l + 8) * 128 + n0]       = acc[nt][2] + b1[n0];
            g_cd[(size_t)(b0 + r0l + 8) * 128 + n0 + 1]   = acc[nt][3] + b1[n0 + 1];
        }
    } else {
        #pragma unroll
        for (int h = 0; h < 2; h++) {
            #pragma unroll
            for (int i = 0; i < 16; i++)
                acc[i][0] = acc[i][1] = acc[i][2] = acc[i][3] = 0.f;
            __syncthreads();
            gemm_chunks(acc, smb, g_Bh + 65536 + h * 16384, 2, h * 256, tid);
            #pragma unroll
            for (int nt = 0; nt < 16; nt++) {
                const int d0 = nt * 8 + (lane & 3) * 2;
                const float g0 = gb[h * 128 + d0], g1 = gb[h * 128 + d0 + 1];
                float* outA = g_gate + (size_t)(b0 + r0l) * 256 + h * 128;
                float* outB = g_gate + (size_t)(b0 + r0l + 8) * 256 + h * 128;
                outA[d0]     = 1.0f / (1.0f + __expf(-(acc[nt][0] + g0)));
                outA[d0 + 1] = 1.0f / (1.0f + __expf(-(acc[nt][1] + g1)));
                outB[d0]     = 1.0f / (1.0f + __expf(-(acc[nt][2] + g0)));
                outB[d0 + 1] = 1.0f / (1.0f + __expf(-(acc[nt][3] + g1)));
            }
        }
    }
}

// ---------------------------------------------------------------------------
// k1: warp-autonomous persistent. 148 blocks x 512 thr. B resident in smem.
__global__ __launch_bounds__(512, 1) void k1_main(
    const int*   __restrict__ cidx,
    const float* __restrict__ emb,
    const int*   __restrict__ nbidx,
    const float* __restrict__ nbwt,
    const float* __restrict__ W2,
    const float* __restrict__ b2,
    int B)
{
    extern __shared__ __align__(16) char smp[];
    const uint32_t smb = smem_u32(smp);
    const int tid = threadIdx.x, warp = tid >> 5, lane = tid & 31;

    #pragma unroll
    for (int t = 0; t < 8; t++) {
        const int i = tid + t * 512;
        const int chunk = i >> 10;
        const int rem = i & 1023;
        const int n = rem >> 3, s = rem & 7;
        cp16(smb + K1_B + chunk * 16384 + n * 128 + ((s * 16) ^ ((n & 7) << 4)),
             g_Bh + chunk * 8192 + n * 64 + s * 8);
    }
    cp_commit();
    if (tid < 128) ((float*)(smp + K1_W2))[tid] = W2[tid];
    if (tid < 2)   ((float*)(smp + K1_B2))[tid] = b2[tid];
    cp_wait0();
    __syncthreads();

    const float* sW2 = (const float*)(smp + K1_W2);
    const float* sB2 = (const float*)(smp + K1_B2);
    float* sLg = (float*)(smp + K1_LG) + warp * 32;
    const uint32_t AwOff = (uint32_t)K1_A + (uint32_t)warp * 8192;

    const uint32_t aLdsm = smb + AwOff + (uint32_t)(lane & 15) * 512;
    const uint32_t aXor  = (uint32_t)((lane & 7) << 4);
    const int bg = lane >> 3, br = lane & 7;
    const int bRowL = br + ((bg >> 1) << 3);
    const uint32_t bColB = (uint32_t)((bg & 1) << 4);
    const uint32_t bXor  = (uint32_t)((bRowL & 7) << 4);

    const int wg = blockIdx.x * 16 + warp;
    const int NW = gridDim.x * 16;

    int gidx = 0, msk = 0; float wt = 0.f;
    {
        const int b = wg;
        if (b < B) {
            int ci = 0;
            if (lane == 0) ci = cidx[b];
            ci = __shfl_sync(0xffffffffu, ci, 0);
            const int safe = ci >= 0 ? ci : 0;
            if (lane < 16) {
                const int ni = nbidx[(size_t)safe * 16 + lane];
                msk = ni >= 0;
                gidx = ni >= 0 ? ni : 0;
                wt = nbwt[(size_t)safe * 16 + lane];
            }
        }
    }

    for (int b = wg; b < B; b += NW) {
        #pragma unroll
        for (int r = 0; r < 16; r++) {
            const int src = __shfl_sync(0xffffffffu, gidx, r);
            const float4 v0 = *(const float4*)(emb + (size_t)src * 256 + lane * 8);
            const float4 v1 = *(const float4*)(emb + (size_t)src * 256 + lane * 8 + 4);
            __half2 h0 = __floats2half2_rn(v0.x, v0.y);
            __half2 h1 = __floats2half2_rn(v0.z, v0.w);
            __half2 h2 = __floats2half2_rn(v1.x, v1.y);
            __half2 h3 = __floats2half2_rn(v1.z, v1.w);
            uint4 pk = make_uint4(*(uint32_t*)&h0, *(uint32_t*)&h1, *(uint32_t*)&h2, *(uint32_t*)&h3);
            *(uint4*)(smp + AwOff + r * 512 + (((uint32_t)(lane * 16)) ^ ((r & 7) << 4))) = pk;
        }
        const int mskC = msk; const float wtC = wt;

        {
            const int bn = b + NW;
            if (bn < B) {
                int ci = 0;
                if (lane == 0) ci = cidx[bn];
                ci = __shfl_sync(0xffffffffu, ci, 0);
                const int safe = ci >= 0 ? ci : 0;
                if (lane < 16) {
                    const int ni = nbidx[(size_t)safe * 16 + lane];
                    msk = ni >= 0;
                    gidx = ni >= 0 ? ni : 0;
                    wt = nbwt[(size_t)safe * 16 + lane];
                }
            }
        }

        float2 cdr[8];
        {
            const float* cdb = g_cd + (size_t)b * 128;
            #pragma unroll
            for (int nt = 0; nt < 8; nt++)
                cdr[nt] = *(const float2*)(cdb + nt * 16 + (lane & 3) * 2);
        }
        __syncwarp();

        float acc[16][4];
        #pragma unroll
        for (int i = 0; i < 16; i++)
            acc[i][0] = acc[i][1] = acc[i][2] = acc[i][3] = 0.f;
        #pragma unroll
        for (int c = 0; c < 4; c++) {
            const uint32_t Bc = smb + K1_B + c * 16384;
            #pragma unroll
            for (int kt = 0; kt < 4; kt++) {
                const uint32_t aCol = (uint32_t)(c * 128 + kt * 32) + ((uint32_t)(lane >> 4) << 4);
                uint32_t a0, a1, a2, a3;
                ldsm_x4(a0, a1, a2, a3, aLdsm + (aCol ^ aXor));
                const uint32_t bCol = ((uint32_t)(kt * 32) + bColB) ^ bXor;
                #pragma unroll
                for (int np = 0; np < 8; np++) {
                    uint32_t b0, b1, b2r, b3;
                    ldsm_x4(b0, b1, b2r, b3, Bc + (uint32_t)((np * 16 + bRowL) * 128) + bCol);
                    mma16816(acc[2 * np],     a0, a1, a2, a3, b0, b1);
                    mma16816(acc[2 * np + 1], a0, a1, a2, a3, b2r, b3);
                }
            }
        }

        float lgA[2] = {0.f, 0.f};
        float lgB[2] = {0.f, 0.f};
        const float* cdb = g_cd + (size_t)b * 128;
        #pragma unroll
        for (int nt = 0; nt < 16; nt++) {
            const int h = nt >> 3;
            const int n0 = nt * 8 + (lane & 3) * 2;
            float2 cd2;
            if ((nt & 1) == 0) cd2 = cdr[nt >> 1];
            else               cd2 = *(const float2*)(cdb + n0);
            const float w20 = sW2[n0], w21 = sW2[n0 + 1];
            lgA[h] += gelu_exact(acc[nt][0] + cd2.x) * w20 + gelu_exact(acc[nt][1] + cd2.y) * w21;
            lgB[h] += gelu_exact(acc[nt][2] + cd2.x) * w20 + gelu_exact(acc[nt][3] + cd2.y) * w21;
        }
        #pragma unroll
        for (int s = 1; s < 4; s <<= 1) {
            lgA[0] += __shfl_xor_sync(0xffffffffu, lgA[0], s);
            lgA[1] += __shfl_xor_sync(0xffffffffu, lgA[1], s);
            lgB[0] += __shfl_xor_sync(0xffffffffu, lgB[0], s);
            lgB[1] += __shfl_xor_sync(0xffffffffu, lgB[1], s);
        }
        if ((lane & 3) == 0) {
            const int k = lane >> 2;
            sLg[k]          = lgA[0];
            sLg[16 + k]     = lgA[1];
            sLg[k + 8]      = lgB[0];
            sLg[16 + k + 8] = lgB[1];
        }
        __syncwarp();

        {
            const int hh = lane >> 4;
            const int k = lane & 15;
            const int mk = __shfl_sync(0xffffffffu, mskC, k);
            const float wk = __shfl_sync(0xffffffffu, wtC, k);
            const float NEG_INF = __int_as_float(0xff800000);
            float lv = sLg[hh * 16 + k] + sB2[hh] + __logf(wk + 1e-8f);
            if (!mk) lv = NEG_INF;
            float mx = lv;
            #pragma unroll
            for (int s = 1; s < 16; s <<= 1)
                mx = fmaxf(mx, __shfl_xor_sync(0xffffffffu, mx, s));
            const bool none = (mx == NEG_INF);
            float ex = mk ? __expf(lv - (none ? 0.f : mx)) : 0.f;
            float sm = ex;
            #pragma unroll
            for (int s = 1; s < 16; s <<= 1)
                sm += __shfl_xor_sync(0xffffffffu, sm, s);
            __syncwarp();
            sLg[hh * 16 + k] = none ? (1.0f / 16.0f) : (ex / sm);
        }
        __syncwarp();

        // --- aggregation + combine (fp16 out): lane owns e = lane*8..lane*8+7 ---
        // Per k: one LDS.128 (XOR swizzle permutes 16B segments only, so the
        // uint4 is contiguous in e). Same k-loop order -> bit-identical math.
        {
            const size_t bofs = (size_t)b * 256;
            const int e0 = lane * 8;                 // head = lane>>4 (constant)
            const float* wgt = sLg + ((lane >> 4) << 4);
            float ax[8] = {0.f, 0.f, 0.f, 0.f, 0.f, 0.f, 0.f, 0.f};
            #pragma unroll
            for (int k = 0; k < 16; k++) {
                const uint32_t ad = AwOff + k * 512
                                  + (((uint32_t)(e0 * 2)) ^ ((uint32_t)(k & 7) << 4));
                const uint4 hv = *(const uint4*)(smp + ad);
                const float w = wgt[k];
                const float2 f0 = __half22float2(*(const __half2*)&hv.x);
                const float2 f1 = __half22float2(*(const __half2*)&hv.y);
                const float2 f2 = __half22float2(*(const __half2*)&hv.z);
                const float2 f3 = __half22float2(*(const __half2*)&hv.w);
                ax[0] = fmaf(w, f0.x, ax[0]); ax[1] = fmaf(w, f0.y, ax[1]);
                ax[2] = fmaf(w, f1.x, ax[2]); ax[3] = fmaf(w, f1.y, ax[3]);
                ax[4] = fmaf(w, f2.x, ax[4]); ax[5] = fmaf(w, f2.y, ax[5]);
                ax[6] = fmaf(w, f3.x, ax[6]); ax[7] = fmaf(w, f3.y, ax[7]);
            }
            const float4 gt0 = *(const float4*)(g_gate + bofs + e0);
            const float4 gt1 = *(const float4*)(g_gate + bofs + e0 + 4);
            const float4 cn0 = *(const float4*)(g_center + bofs + e0);
            const float4 cn1 = *(const float4*)(g_center + bofs + e0 + 4);
            __half2 o0 = __floats2half2_rn(fmaf(gt0.x, ax[0], cn0.x), fmaf(gt0.y, ax[1], cn0.y));
            __half2 o1 = __floats2half2_rn(fmaf(gt0.z, ax[2], cn0.z), fmaf(gt0.w, ax[3], cn0.w));
            __half2 o2 = __floats2half2_rn(fmaf(gt1.x, ax[4], cn1.x), fmaf(gt1.y, ax[5], cn1.y));
            __half2 o3 = __floats2half2_rn(fmaf(gt1.z, ax[6], cn1.z), fmaf(gt1.w, ax[7], cn1.w));
            uint4 ov = make_uint4(*(uint32_t*)&o0, *(uint32_t*)&o1, *(uint32_t*)&o2, *(uint32_t*)&o3);
            *(uint4*)(g_comb_h + bofs + e0) = ov;
        }
        __syncwarp();
    }
}

// ---------------------------------------------------------------------------
// k3: out = comb_h @ oW^T + ob (HMMA). grid.y = n-half.
__global__ __launch_bounds__(256) void k3_out_h(
    const float* __restrict__ ob,
    const int*   __restrict__ cidx,
    float*       __restrict__ out)
{
    extern __shared__ __align__(16) char smp[];
    const uint32_t smb = smem_u32(smp);
    const int tid = threadIdx.x, warp = tid >> 5, lane = tid & 31;
    const int b0 = blockIdx.x * 128;
    const int nh = blockIdx.y;

    for (int i = tid; i < 4096; i += 256) {
        const int row = i >> 5, seg = i & 31;
        *(uint4*)(smp + SA + row * 528 + seg * 16) =
            *(const uint4*)(g_comb_h + (size_t)(b0 + row) * 256 + seg * 8);
    }
    __syncthreads();

    const int r0 = b0 + warp * 16 + (lane >> 2);
    const int ci0 = cidx[r0], ci1 = cidx[r0 + 8];

    float acc[16][4];
    #pragma unroll
    for (int i = 0; i < 16; i++)
        acc[i][0] = acc[i][1] = acc[i][2] = acc[i][3] = 0.f;
    gemm_chunks(acc, smb, g_oWh + nh * 32768, 4, 0, tid);
    #pragma unroll
    for (int nt = 0; nt < 16; nt++) {
        const int n0 = nh * 128 + nt * 8 + (lane & 3) * 2;
        float yA0 = acc[nt][0] + ob[n0];
        float yA1 = acc[nt][1] + ob[n0 + 1];
        float yB0 = acc[nt][2] + ob[n0];
        float yB1 = acc[nt][3] + ob[n0 + 1];
        if (ci0 < 0) {
            yA0 = g_center[(size_t)r0 * 256 + n0];
            yA1 = g_center[(size_t)r0 * 256 + n0 + 1];
        }
        if (ci1 < 0) {
            yB0 = g_center[(size_t)(r0 + 8) * 256 + n0];
            yB1 = g_center[(size_t)(r0 + 8) * 256 + n0 + 1];
        }
        out[(size_t)r0 * 256 + n0]           = yA0;
        out[(size_t)r0 * 256 + n0 + 1]       = yA1;
        out[(size_t)(r0 + 8) * 256 + n0]     = yB0;
        out[(size_t)(r0 + 8) * 256 + n0 + 1] = yB1;
    }
}

// ---------------------------------------------------------------------------
extern "C" void kernel_launch(void* const* d_in, const int* in_sizes, int n_in,
                              void* d_out, int out_size)
{
    const int*   center_idx = (const int*)  d_in[0];
    const float* emb        = (const float*)d_in[1];
    const int*   nbidx      = (const int*)  d_in[2];
    const float* nbwt       = (const float*)d_in[3];
    const float* W1         = (const float*)d_in[4];
    const float* b1         = (const float*)d_in[5];
    const float* W2         = (const float*)d_in[6];
    const float* b2         = (const float*)d_in[7];
    const float* gW         = (const float*)d_in[8];
    const float* gb         = (const float*)d_in[9];
    const float* oW         = (const float*)d_in[10];
    const float* ob         = (const float*)d_in[11];
    float* out = (float*)d_out;
    const int B = in_sizes[0];

    cudaFuncSetAttribute(k0_center, cudaFuncAttributeMaxDynamicSharedMemorySize, SM_BYTES);
    cudaFuncSetAttribute(k1_main,   cudaFuncAttributeMaxDynamicSharedMemorySize, K1_BYTES);
    cudaFuncSetAttribute(k3_out_h,  cudaFuncAttributeMaxDynamicSharedMemorySize, SM_BYTES);

    prep_pack<<<640, 256>>>(W1, gW, oW);
    k0_center<<<dim3(B / 128, 2), 256, SM_BYTES>>>(center_idx, emb, b1, gb);
    k1_main<<<148, 512, K1_BYTES>>>(center_idx, emb, nbidx, nbwt, W2, b2, B);
    k3_out_h<<<dim3(B / 128, 2), 256, SM_BYTES>>>(ob, center_idx, out);
}

// round 15
// speedup vs baseline: 1.3464x; 1.1284x over previous
#include <cuda_runtime.h>
#include <cuda_fp16.h>
#include <cstdint>

#define BBATCH 16384

__device__ float g_center[BBATCH * 256];
__device__ float g_cd[BBATCH * 128];
__device__ float g_gate[BBATCH * 256];
__device__ __align__(16) __half g_comb_h[BBATCH * 256];
// fp16 weight images, chunk-major [chunk][n(128)][64]:
//   [0,32768): W1 neighbor | [32768,65536): W1 center | [65536,98304): gate_W h0,h1
__device__ __align__(16) __half g_Bh[98304];
// out_W image: [nhalf][chunk][n(128)][64]
__device__ __align__(16) __half g_oWh[65536];

// ---- smem layout for k0/k3 (double-buffered chunked gemm; 2 CTA/SM) ----
#define SA    0          // 67584: A fp16 [128 rows][264] (stride 528B)
#define SBUF  67584      // 36864: 2 x B chunk [128 n][72 k fp16] (stride 144B)
#define SIDX  111104     // 512
#define SM_BYTES 112640

// ---- smem layout for k1 (16 warps, 512 threads) ----
#define K1_B    0          // 65536: full W1nb image, 4 chunks, XOR-swizzled
#define K1_A    65536      // 131072: 16 warps x 8KB A region (16 rows x 512B, XOR)
#define K1_W2   196608     // 512
#define K1_B2   197120     // 8
#define K1_LG   197632     // 2048
#define K1_BYTES 199680

__device__ __forceinline__ uint32_t smem_u32(const void* p) {
    uint32_t a;
    asm("{ .reg .u64 t; cvta.to.shared.u64 t, %1; cvt.u32.u64 %0, t; }" : "=r"(a) : "l"(p));
    return a;
}
__device__ __forceinline__ void ldsm_x4(uint32_t& r0, uint32_t& r1, uint32_t& r2, uint32_t& r3, uint32_t addr) {
    asm volatile("ldmatrix.sync.aligned.m8n8.x4.shared.b16 {%0,%1,%2,%3}, [%4];"
                 : "=r"(r0), "=r"(r1), "=r"(r2), "=r"(r3) : "r"(addr));
}
__device__ __forceinline__ void mma16816(float* d, uint32_t a0, uint32_t a1, uint32_t a2, uint32_t a3,
                                         uint32_t b0, uint32_t b1) {
    asm volatile(
        "mma.sync.aligned.m16n8k16.row.col.f32.f16.f16.f32 "
        "{%0,%1,%2,%3}, {%4,%5,%6,%7}, {%8,%9}, {%0,%1,%2,%3};"
        : "+f"(d[0]), "+f"(d[1]), "+f"(d[2]), "+f"(d[3])
        : "r"(a0), "r"(a1), "r"(a2), "r"(a3), "r"(b0), "r"(b1));
}
__device__ __forceinline__ void cp16(uint32_t saddr, const void* g) {
    asm volatile("cp.async.ca.shared.global [%0], [%1], 16;" :: "r"(saddr), "l"(g));
}
__device__ __forceinline__ void cp_commit() { asm volatile("cp.async.commit_group;"); }
__device__ __forceinline__ void cp_wait0()  { asm volatile("cp.async.wait_group 0;" ::: "memory"); }
// exact GELU via erff polynomial (k0 path precision)
__device__ __forceinline__ float gelu_exact(float x) {
    return 0.5f * x * (1.0f + erff(x * 0.70710678118654752440f));
}
// tanh-form GELU with single-instruction MUFU tanh (sm_75+): 5 FFMA + 1 MUFU.
// |err| vs exact erf-GELU <= ~7e-4 abs worst case; logit impact ~5e-5.
__device__ __forceinline__ float gelu_tanh(float x) {
    const float z = x * fmaf(0.03567740814f, x * x, 0.7978845608f);
    float t;
    asm("tanh.approx.f32 %0, %1;" : "=f"(t) : "f"(z));
    return 0.5f * x * (1.0f + t);
}

// ---------------------------------------------------------------------------
__global__ __launch_bounds__(256) void prep_pack(const float* __restrict__ W1,
                                                 const float* __restrict__ gW,
                                                 const float* __restrict__ oW) {
    int i = blockIdx.x * 256 + threadIdx.x;
    if (i < 65536) {
        int img = i >> 15;
        int r = i & 32767;
        int chunk = r >> 13;
        int rr = r & 8191;
        int n = rr >> 6, kl = rr & 63;
        int k = chunk * 64 + kl;
        int h = n >> 6, a = n & 63;
        int es = img ? k : (256 + k);
        g_Bh[i] = __float2half_rn(W1[(size_t)h * 32768 + (size_t)es * 64 + a]);
    } else if (i < 98304) {
        int j = i - 65536;
        int h = j >> 14;
        int rr = j & 16383;
        int chunk = rr >> 13;
        int r2 = rr & 8191;
        int d = r2 >> 6, el = r2 & 63;
        int e = chunk * 64 + el;
        g_Bh[i] = __float2half_rn(gW[(size_t)h * 16384 + (size_t)d * 128 + e]);
    } else {
        int j = i - 98304;
        int nh = j >> 15;
        int r = j & 32767;
        int chunk = r >> 13;
        int rr = r & 8191;
        int n = rr >> 6, kl = rr & 63;
        int k = chunk * 64 + kl;
        int N = nh * 128 + n;
        g_oWh[j] = __float2half_rn(oW[(size_t)N * 256 + k]);
    }
}

// ---- chunked gemm machinery (k0/k3), double-buffered ----
__device__ __forceinline__ void load_chunk(uint32_t sdst, const __half* src, int tid) {
    #pragma unroll
    for (int t = 0; t < 4; t++) {
        const int i = tid + t * 256;
        const int row = i >> 3, seg = i & 7;
        cp16(sdst + row * 144 + seg * 16, src + row * 64 + seg * 8);
    }
}
__device__ __forceinline__ void gemm_chunks(float acc[16][4], uint32_t smb,
                                            const __half* gB, int nchunks,
                                            int a_k_byte, int tid) {
    const int warp = tid >> 5, lane = tid & 31;
    const uint32_t aBase = smb + SA + (uint32_t)(warp * 16 + (lane & 15)) * 528
                         + (uint32_t)((lane >> 4) * 16) + (uint32_t)a_k_byte;
    const int bg = lane >> 3, br = lane & 7;
    const uint32_t bOff = (uint32_t)(br + ((bg >> 1) * 8)) * 144 + (uint32_t)((bg & 1) * 16);

    load_chunk(smb + SBUF, gB, tid);
    cp_commit();
    for (int c = 0; c < nchunks; c++) {
        cp_wait0();
        __syncthreads();
        if (c + 1 < nchunks) {
            load_chunk(smb + SBUF + ((c + 1) & 1) * 18432, gB + (c + 1) * 8192, tid);
            cp_commit();
        }
        const uint32_t bBase = smb + SBUF + (c & 1) * 18432 + bOff;
        const uint32_t aC = aBase + c * 128;
        #pragma unroll
        for (int kt = 0; kt < 4; kt++) {
            uint32_t a0, a1, a2, a3;
            ldsm_x4(a0, a1, a2, a3, aC + kt * 32);
            #pragma unroll
            for (int np = 0; np < 8; np++) {
                uint32_t b0, b1, b2, b3;
                ldsm_x4(b0, b1, b2, b3, bBase + (uint32_t)(np * 2304) + kt * 32);
                mma16816(acc[2 * np],     a0, a1, a2, a3, b0, b1);
                mma16816(acc[2 * np + 1], a0, a1, a2, a3, b2, b3);
            }
        }
        __syncthreads();
    }
}

// ---------------------------------------------------------------------------
// k0: centers -> g_center, g_cd, g_gate. grid.y: y0 = cd (+store center),
// y1 = both gate gemms.
__global__ __launch_bounds__(256) void k0_center(
    const int* __restrict__ cidx, const float* __restrict__ emb,
    const float* __restrict__ b1, const float* __restrict__ gb)
{
    extern __shared__ __align__(16) char smp[];
    const uint32_t smb = smem_u32(smp);
    const int tid = threadIdx.x, warp = tid >> 5, lane = tid & 31;
    const int b0 = blockIdx.x * 128;
    const int job = blockIdx.y;

    int* sIdx = (int*)(smp + SIDX);
    if (tid < 128) sIdx[tid] = cidx[b0 + tid];
    __syncthreads();

    for (int i = tid; i < 8192; i += 256) {
        const int row = i >> 6;
        const int e0 = (i & 63) * 4;
        const int ci = sIdx[row];
        float4 v = make_float4(0.f, 0.f, 0.f, 0.f);
        if (ci >= 0) v = *(const float4*)(emb + (size_t)ci * 256 + e0);
        if (job == 0) *(float4*)(g_center + (size_t)(b0 + row) * 256 + e0) = v;
        __half2 h0 = __floats2half2_rn(v.x, v.y);
        __half2 h1 = __floats2half2_rn(v.z, v.w);
        *(uint2*)(smp + SA + row * 528 + e0 * 2) = make_uint2(*(uint32_t*)&h0, *(uint32_t*)&h1);
    }
    __syncthreads();

    const int r0l = warp * 16 + (lane >> 2);
    float acc[16][4];

    if (job == 0) {
        #pragma unroll
        for (int i = 0; i < 16; i++)
            acc[i][0] = acc[i][1] = acc[i][2] = acc[i][3] = 0.f;
        gemm_chunks(acc, smb, g_Bh + 32768, 4, 0, tid);
        #pragma unroll
        for (int nt = 0; nt < 16; nt++) {
            const int n0 = nt * 8 + (lane & 3) * 2;
            g_cd[(size_t)(b0 + r0l) * 128 + n0]           = acc[nt][0] + b1[n0];
            g_cd[(size_t)(b0 + r0l) * 128 + n0 + 1]       = acc[nt][1] + b1[n0 + 1];
            g_cd[(size_t)(b0 + r0l + 8) * 128 + n0]       = acc[nt][2] + b1[n0];
            g_cd[(size_t)(b0 + r0l + 8) * 128 + n0 + 1]   = acc[nt][3] + b1[n0 + 1];
        }
    } else {
        #pragma unroll
        for (int h = 0; h < 2; h++) {
            #pragma unroll
            for (int i = 0; i < 16; i++)
                acc[i][0] = acc[i][1] = acc[i][2] = acc[i][3] = 0.f;
            __syncthreads();
            gemm_chunks(acc, smb, g_Bh + 65536 + h * 16384, 2, h * 256, tid);
            #pragma unroll
            for (int nt = 0; nt < 16; nt++) {
                const int d0 = nt * 8 + (lane & 3) * 2;
                const float g0 = gb[h * 128 + d0], g1 = gb[h * 128 + d0 + 1];
                float* outA = g_gate + (size_t)(b0 + r0l) * 256 + h * 128;
                float* outB = g_gate + (size_t)(b0 + r0l + 8) * 256 + h * 128;
                outA[d0]     = 1.0f / (1.0f + __expf(-(acc[nt][0] + g0)));
                outA[d0 + 1] = 1.0f / (1.0f + __expf(-(acc[nt][1] + g1)));
                outB[d0]     = 1.0f / (1.0f + __expf(-(acc[nt][2] + g0)));
                outB[d0 + 1] = 1.0f / (1.0f + __expf(-(acc[nt][3] + g1)));
            }
        }
    }
}

// ---------------------------------------------------------------------------
// k1: warp-autonomous persistent. 148 blocks x 512 thr. B resident in smem.
__global__ __launch_bounds__(512, 1) void k1_main(
    const int*   __restrict__ cidx,
    const float* __restrict__ emb,
    const int*   __restrict__ nbidx,
    const float* __restrict__ nbwt,
    const float* __restrict__ W2,
    const float* __restrict__ b2,
    int B)
{
    extern __shared__ __align__(16) char smp[];
    const uint32_t smb = smem_u32(smp);
    const int tid = threadIdx.x, warp = tid >> 5, lane = tid & 31;

    #pragma unroll
    for (int t = 0; t < 8; t++) {
        const int i = tid + t * 512;
        const int chunk = i >> 10;
        const int rem = i & 1023;
        const int n = rem >> 3, s = rem & 7;
        cp16(smb + K1_B + chunk * 16384 + n * 128 + ((s * 16) ^ ((n & 7) << 4)),
             g_Bh + chunk * 8192 + n * 64 + s * 8);
    }
    cp_commit();
    if (tid < 128) ((float*)(smp + K1_W2))[tid] = W2[tid];
    if (tid < 2)   ((float*)(smp + K1_B2))[tid] = b2[tid];
    cp_wait0();
    __syncthreads();

    const float* sW2 = (const float*)(smp + K1_W2);
    const float* sB2 = (const float*)(smp + K1_B2);
    float* sLg = (float*)(smp + K1_LG) + warp * 32;
    const uint32_t AwOff = (uint32_t)K1_A + (uint32_t)warp * 8192;

    const uint32_t aLdsm = smb + AwOff + (uint32_t)(lane & 15) * 512;
    const uint32_t aXor  = (uint32_t)((lane & 7) << 4);
    const int bg = lane >> 3, br = lane & 7;
    const int bRowL = br + ((bg >> 1) << 3);
    const uint32_t bColB = (uint32_t)((bg & 1) << 4);
    const uint32_t bXor  = (uint32_t)((bRowL & 7) << 4);

    const int wg = blockIdx.x * 16 + warp;
    const int NW = gridDim.x * 16;

    int gidx = 0, msk = 0; float wt = 0.f;
    {
        const int b = wg;
        if (b < B) {
            int ci = 0;
            if (lane == 0) ci = cidx[b];
            ci = __shfl_sync(0xffffffffu, ci, 0);
            const int safe = ci >= 0 ? ci : 0;
            if (lane < 16) {
                const int ni = nbidx[(size_t)safe * 16 + lane];
                msk = ni >= 0;
                gidx = ni >= 0 ? ni : 0;
                wt = nbwt[(size_t)safe * 16 + lane];
            }
        }
    }

    for (int b = wg; b < B; b += NW) {
        #pragma unroll
        for (int r = 0; r < 16; r++) {
            const int src = __shfl_sync(0xffffffffu, gidx, r);
            const float4 v0 = *(const float4*)(emb + (size_t)src * 256 + lane * 8);
            const float4 v1 = *(const float4*)(emb + (size_t)src * 256 + lane * 8 + 4);
            __half2 h0 = __floats2half2_rn(v0.x, v0.y);
            __half2 h1 = __floats2half2_rn(v0.z, v0.w);
            __half2 h2 = __floats2half2_rn(v1.x, v1.y);
            __half2 h3 = __floats2half2_rn(v1.z, v1.w);
            uint4 pk = make_uint4(*(uint32_t*)&h0, *(uint32_t*)&h1, *(uint32_t*)&h2, *(uint32_t*)&h3);
            *(uint4*)(smp + AwOff + r * 512 + (((uint32_t)(lane * 16)) ^ ((r & 7) << 4))) = pk;
        }
        const int mskC = msk; const float wtC = wt;

        {
            const int bn = b + NW;
            if (bn < B) {
                int ci = 0;
                if (lane == 0) ci = cidx[bn];
                ci = __shfl_sync(0xffffffffu, ci, 0);
                const int safe = ci >= 0 ? ci : 0;
                if (lane < 16) {
                    const int ni = nbidx[(size_t)safe * 16 + lane];
                    msk = ni >= 0;
                    gidx = ni >= 0 ? ni : 0;
                    wt = nbwt[(size_t)safe * 16 + lane];
                }
            }
        }

        float2 cdr[8];
        {
            const float* cdb = g_cd + (size_t)b * 128;
            #pragma unroll
            for (int nt = 0; nt < 8; nt++)
                cdr[nt] = *(const float2*)(cdb + nt * 16 + (lane & 3) * 2);
        }
        __syncwarp();

        float acc[16][4];
        #pragma unroll
        for (int i = 0; i < 16; i++)
            acc[i][0] = acc[i][1] = acc[i][2] = acc[i][3] = 0.f;
        #pragma unroll
        for (int c = 0; c < 4; c++) {
            const uint32_t Bc = smb + K1_B + c * 16384;
            #pragma unroll
            for (int kt = 0; kt < 4; kt++) {
                const uint32_t aCol = (uint32_t)(c * 128 + kt * 32) + ((uint32_t)(lane >> 4) << 4);
                uint32_t a0, a1, a2, a3;
                ldsm_x4(a0, a1, a2, a3, aLdsm + (aCol ^ aXor));
                const uint32_t bCol = ((uint32_t)(kt * 32) + bColB) ^ bXor;
                #pragma unroll
                for (int np = 0; np < 8; np++) {
                    uint32_t b0, b1, b2r, b3;
                    ldsm_x4(b0, b1, b2r, b3, Bc + (uint32_t)((np * 16 + bRowL) * 128) + bCol);
                    mma16816(acc[2 * np],     a0, a1, a2, a3, b0, b1);
                    mma16816(acc[2 * np + 1], a0, a1, a2, a3, b2r, b3);
                }
            }
        }

        float lgA[2] = {0.f, 0.f};
        float lgB[2] = {0.f, 0.f};
        const float* cdb = g_cd + (size_t)b * 128;
        #pragma unroll
        for (int nt = 0; nt < 16; nt++) {
            const int h = nt >> 3;
            const int n0 = nt * 8 + (lane & 3) * 2;
            float2 cd2;
            if ((nt & 1) == 0) cd2 = cdr[nt >> 1];
            else               cd2 = *(const float2*)(cdb + n0);
            const float w20 = sW2[n0], w21 = sW2[n0 + 1];
            lgA[h] += gelu_tanh(acc[nt][0] + cd2.x) * w20 + gelu_tanh(acc[nt][1] + cd2.y) * w21;
            lgB[h] += gelu_tanh(acc[nt][2] + cd2.x) * w20 + gelu_tanh(acc[nt][3] + cd2.y) * w21;
        }
        #pragma unroll
        for (int s = 1; s < 4; s <<= 1) {
            lgA[0] += __shfl_xor_sync(0xffffffffu, lgA[0], s);
            lgA[1] += __shfl_xor_sync(0xffffffffu, lgA[1], s);
            lgB[0] += __shfl_xor_sync(0xffffffffu, lgB[0], s);
            lgB[1] += __shfl_xor_sync(0xffffffffu, lgB[1], s);
        }
        if ((lane & 3) == 0) {
            const int k = lane >> 2;
            sLg[k]          = lgA[0];
            sLg[16 + k]     = lgA[1];
            sLg[k + 8]      = lgB[0];
            sLg[16 + k + 8] = lgB[1];
        }
        __syncwarp();

        {
            const int hh = lane >> 4;
            const int k = lane & 15;
            const int mk = __shfl_sync(0xffffffffu, mskC, k);
            const float wk = __shfl_sync(0xffffffffu, wtC, k);
            const float NEG_INF = __int_as_float(0xff800000);
            float lv = sLg[hh * 16 + k] + sB2[hh] + __logf(wk + 1e-8f);
            if (!mk) lv = NEG_INF;
            float mx = lv;
            #pragma unroll
            for (int s = 1; s < 16; s <<= 1)
                mx = fmaxf(mx, __shfl_xor_sync(0xffffffffu, mx, s));
            const bool none = (mx == NEG_INF);
            float ex = mk ? __expf(lv - (none ? 0.f : mx)) : 0.f;
            float sm = ex;
            #pragma unroll
            for (int s = 1; s < 16; s <<= 1)
                sm += __shfl_xor_sync(0xffffffffu, sm, s);
            __syncwarp();
            sLg[hh * 16 + k] = none ? (1.0f / 16.0f) : (ex / sm);
        }
        __syncwarp();

        // --- aggregation + combine (fp16 out): lane owns e = lane*8..lane*8+7 ---
        {
            const size_t bofs = (size_t)b * 256;
            const int e0 = lane * 8;
            const float* wgt = sLg + ((lane >> 4) << 4);
            float ax[8] = {0.f, 0.f, 0.f, 0.f, 0.f, 0.f, 0.f, 0.f};
            #pragma unroll
            for (int k = 0; k < 16; k++) {
                const uint32_t ad = AwOff + k * 512
                                  + (((uint32_t)(e0 * 2)) ^ ((uint32_t)(k & 7) << 4));
                const uint4 hv = *(const uint4*)(smp + ad);
                const float w = wgt[k];
                const float2 f0 = __half22float2(*(const __half2*)&hv.x);
                const float2 f1 = __half22float2(*(const __half2*)&hv.y);
                const float2 f2 = __half22float2(*(const __half2*)&hv.z);
                const float2 f3 = __half22float2(*(const __half2*)&hv.w);
                ax[0] = fmaf(w, f0.x, ax[0]); ax[1] = fmaf(w, f0.y, ax[1]);
                ax[2] = fmaf(w, f1.x, ax[2]); ax[3] = fmaf(w, f1.y, ax[3]);
                ax[4] = fmaf(w, f2.x, ax[4]); ax[5] = fmaf(w, f2.y, ax[5]);
                ax[6] = fmaf(w, f3.x, ax[6]); ax[7] = fmaf(w, f3.y, ax[7]);
            }
            const float4 gt0 = *(const float4*)(g_gate + bofs + e0);
            const float4 gt1 = *(const float4*)(g_gate + bofs + e0 + 4);
            const float4 cn0 = *(const float4*)(g_center + bofs + e0);
            const float4 cn1 = *(const float4*)(g_center + bofs + e0 + 4);
            __half2 o0 = __floats2half2_rn(fmaf(gt0.x, ax[0], cn0.x), fmaf(gt0.y, ax[1], cn0.y));
            __half2 o1 = __floats2half2_rn(fmaf(gt0.z, ax[2], cn0.z), fmaf(gt0.w, ax[3], cn0.w));
            __half2 o2 = __floats2half2_rn(fmaf(gt1.x, ax[4], cn1.x), fmaf(gt1.y, ax[5], cn1.y));
            __half2 o3 = __floats2half2_rn(fmaf(gt1.z, ax[6], cn1.z), fmaf(gt1.w, ax[7], cn1.w));
            uint4 ov = make_uint4(*(uint32_t*)&o0, *(uint32_t*)&o1, *(uint32_t*)&o2, *(uint32_t*)&o3);
            *(uint4*)(g_comb_h + bofs + e0) = ov;
        }
        __syncwarp();
    }
}

// ---------------------------------------------------------------------------
// k3: out = comb_h @ oW^T + ob (HMMA). grid.y = n-half.
__global__ __launch_bounds__(256) void k3_out_h(
    const float* __restrict__ ob,
    const int*   __restrict__ cidx,
    float*       __restrict__ out)
{
    extern __shared__ __align__(16) char smp[];
    const uint32_t smb = smem_u32(smp);
    const int tid = threadIdx.x, warp = tid >> 5, lane = tid & 31;
    const int b0 = blockIdx.x * 128;
    const int nh = blockIdx.y;

    for (int i = tid; i < 4096; i += 256) {
        const int row = i >> 5, seg = i & 31;
        *(uint4*)(smp + SA + row * 528 + seg * 16) =
            *(const uint4*)(g_comb_h + (size_t)(b0 + row) * 256 + seg * 8);
    }
    __syncthreads();

    const int r0 = b0 + warp * 16 + (lane >> 2);
    const int ci0 = cidx[r0], ci1 = cidx[r0 + 8];

    float acc[16][4];
    #pragma unroll
    for (int i = 0; i < 16; i++)
        acc[i][0] = acc[i][1] = acc[i][2] = acc[i][3] = 0.f;
    gemm_chunks(acc, smb, g_oWh + nh * 32768, 4, 0, tid);
    #pragma unroll
    for (int nt = 0; nt < 16; nt++) {
        const int n0 = nh * 128 + nt * 8 + (lane & 3) * 2;
        float yA0 = acc[nt][0] + ob[n0];
        float yA1 = acc[nt][1] + ob[n0 + 1];
        float yB0 = acc[nt][2] + ob[n0];
        float yB1 = acc[nt][3] + ob[n0 + 1];
        if (ci0 < 0) {
            yA0 = g_center[(size_t)r0 * 256 + n0];
            yA1 = g_center[(size_t)r0 * 256 + n0 + 1];
        }
        if (ci1 < 0) {
            yB0 = g_center[(size_t)(r0 + 8) * 256 + n0];
            yB1 = g_center[(size_t)(r0 + 8) * 256 + n0 + 1];
        }
        out[(size_t)r0 * 256 + n0]           = yA0;
        out[(size_t)r0 * 256 + n0 + 1]       = yA1;
        out[(size_t)(r0 + 8) * 256 + n0]     = yB0;
        out[(size_t)(r0 + 8) * 256 + n0 + 1] = yB1;
    }
}

// ---------------------------------------------------------------------------
extern "C" void kernel_launch(void* const* d_in, const int* in_sizes, int n_in,
                              void* d_out, int out_size)
{
    const int*   center_idx = (const int*)  d_in[0];
    const float* emb        = (const float*)d_in[1];
    const int*   nbidx      = (const int*)  d_in[2];
    const float* nbwt       = (const float*)d_in[3];
    const float* W1         = (const float*)d_in[4];
    const float* b1         = (const float*)d_in[5];
    const float* W2         = (const float*)d_in[6];
    const float* b2         = (const float*)d_in[7];
    const float* gW         = (const float*)d_in[8];
    const float* gb         = (const float*)d_in[9];
    const float* oW         = (const float*)d_in[10];
    const float* ob         = (const float*)d_in[11];
    float* out = (float*)d_out;
    const int B = in_sizes[0];

    cudaFuncSetAttribute(k0_center, cudaFuncAttributeMaxDynamicSharedMemorySize, SM_BYTES);
    cudaFuncSetAttribute(k1_main,   cudaFuncAttributeMaxDynamicSharedMemorySize, K1_BYTES);
    cudaFuncSetAttribute(k3_out_h,  cudaFuncAttributeMaxDynamicSharedMemorySize, SM_BYTES);

    prep_pack<<<640, 256>>>(W1, gW, oW);
    k0_center<<<dim3(B / 128, 2), 256, SM_BYTES>>>(center_idx, emb, b1, gb);
    k1_main<<<148, 512, K1_BYTES>>>(center_idx, emb, nbidx, nbwt, W2, b2, B);
    k3_out_h<<<dim3(B / 128, 2), 256, SM_BYTES>>>(ob, center_idx, out);
}